// round 10
// baseline (speedup 1.0000x reference)
#include <cuda_runtime.h>
#include <cuda_bf16.h>
#include <cuda_fp16.h>
#include <stdint.h>
#include <math.h>

// ---------------- scratch (__device__ globals; allocation-free) ----------------
__device__ __half gAq[(size_t)4096*2048];
__device__ __half gBq[(size_t)3072*2048];
__device__ float  gCq[(size_t)4096*3072];
__device__ __half gAs[(size_t)32*1024*128];
__device__ __half gBs[(size_t)32*2048*128];
__device__ __half gS [(size_t)32*1024*2048];
__device__ __half gAe[(size_t)32*2048*64];
__device__ __half gBe[(size_t)1152*64];        // rows >=1025 stay zero
__device__ __half gR [(size_t)32*2048*1152];
__device__ __half gP [(size_t)32*1024*2048];
__device__ __half gBpv[(size_t)32*128*2048];
__device__ float  gCpv[(size_t)32*1024*128];
__device__ __half gAo[(size_t)4096*2048];
__device__ __half gBo[(size_t)1024*2048];
__device__ float  gCo[(size_t)4096*1024];

// ---------------- helpers ----------------
__device__ __forceinline__ uint32_t smem_u32(const void* p){
    uint32_t a;
    asm("{ .reg .u64 t; cvta.to.shared.u64 t, %1; cvt.u32.u64 %0, t; }" : "=r"(a) : "l"(p));
    return a;
}
__device__ __forceinline__ void hsplit(float v, __half& h, __half& l){
    h = __float2half_rn(v);
    l = __float2half_rn(v - __half2float(h));
}
__device__ __forceinline__ void ldm_x4(uint32_t* r, uint32_t addr){
    asm volatile("ldmatrix.sync.aligned.m8n8.x4.shared.b16 {%0,%1,%2,%3}, [%4];"
                 : "=r"(r[0]), "=r"(r[1]), "=r"(r[2]), "=r"(r[3]) : "r"(addr));
}
__device__ __forceinline__ void mma_f16(float* c, const uint32_t* a, const uint32_t* b){
    asm volatile(
        "mma.sync.aligned.m16n8k16.row.col.f32.f16.f16.f32 "
        "{%0,%1,%2,%3}, {%4,%5,%6,%7}, {%8,%9}, {%0,%1,%2,%3};"
        : "+f"(c[0]), "+f"(c[1]), "+f"(c[2]), "+f"(c[3])
        : "r"(a[0]), "r"(a[1]), "r"(a[2]), "r"(a[3]), "r"(b[0]), "r"(b[1]));
}
__device__ __forceinline__ void cp16(uint32_t saddr, const void* gptr){
    asm volatile("cp.async.cg.shared.global [%0], [%1], 16;"
                 :: "r"(saddr), "l"(gptr) : "memory");
}

// =====================================================================
// Generic batched GEMM: C[z][M][N] = A[z][M][K] * B[z][N][K]^T
// fp16 in (K-major), fp32 accum via HMMA m16n8k16; C fp32 or fp16.
// Tile 128x128, K-chunk 64, 3-stage cp.async pipeline, single bar/chunk.
// =====================================================================
#define GSMEM (3*32768 + 1024)
__global__ __launch_bounds__(256, 2) void k_gemm(
    const __half* __restrict__ A, const __half* __restrict__ B, void* __restrict__ Cv,
    int K, int ldc, long long sA, long long sB, long long sC, int outHalf)
{
    extern __shared__ char smraw[];
    const uint32_t aBase = (smem_u32(smraw) + 1023u) & ~1023u;
    const int tid = threadIdx.x, wid = tid >> 5, lid = tid & 31;
    const int wm = wid & 1, wn = wid >> 1;           // 2 x 4 warp grid
    const int m0 = blockIdx.x << 7, n0 = blockIdx.y << 7, z = blockIdx.z;
    A += (size_t)z * (size_t)sA;
    B += (size_t)z * (size_t)sB;

    float acc[4][4][4];
    #pragma unroll
    for (int i = 0; i < 4; ++i)
    #pragma unroll
    for (int j = 0; j < 4; ++j)
    #pragma unroll
    for (int k = 0; k < 4; ++k) acc[i][j][k] = 0.f;

    // A: row = wm*64 + mt*16 + (lid&15); k-unit(16B) = s*2 + (lid>>4)
    const int arow = wm*64 + (lid & 15);
    const uint32_t ahi = (uint32_t)(lid >> 4) << 4;           // 0 or 16 bytes
    // B: row = wn*32 + (2p + (g>>1))*8 + (lid&7); unit = s*2 + (g&1)
    const int g = lid >> 3;
    const int brow = wn*32 + ((g >> 1) << 3) + (lid & 7);
    const uint32_t bhi = (uint32_t)(g & 1) << 4;

    const int nch = K >> 6, kq = K >> 3;
    const int lr = tid >> 3, lq = tid & 7;

    auto issue = [&](int cidx){
        const int st = cidx - (cidx/3)*3;
        const uint32_t dA = aBase + (uint32_t)st * 32768u;
        const uint32_t dB = dA + 16384u;
        const uint4* a4 = (const uint4*)(A + (size_t)m0 * K) + cidx * 8;
        const uint4* b4 = (const uint4*)(B + (size_t)n0 * K) + cidx * 8;
        #pragma unroll
        for (int it = 0; it < 4; ++it){
            int r = lr + it*32;
            uint32_t off = (uint32_t)((r << 7) | (lq << 4));
            uint32_t sw = off ^ ((off >> 3) & 0x70);
            cp16(dA + sw, a4 + (size_t)r * kq + lq);
            cp16(dB + sw, b4 + (size_t)r * kq + lq);
        }
    };

    if (0 < nch) issue(0);
    asm volatile("cp.async.commit_group;" ::: "memory");
    if (1 < nch) issue(1);
    asm volatile("cp.async.commit_group;" ::: "memory");

    for (int c = 0; c < nch; ++c){
        // groups committed so far: G0..G_{c+1}; keep newest 1 -> G_c complete
        asm volatile("cp.async.wait_group %0;" :: "n"(1));
        __syncthreads();   // buffer c%3 visible; all threads done with compute(c-1)

        const int st = c - (c/3)*3;
        const uint32_t aA = aBase + (uint32_t)st * 32768u;
        const uint32_t aB = aA + 16384u;
        #pragma unroll
        for (int s = 0; s < 4; ++s){
            const uint32_t slo = (uint32_t)s << 5;            // s*32 bytes
            uint32_t af[4][4], bf[4][2];
            #pragma unroll
            for (int mt = 0; mt < 4; ++mt){
                int row = arow + mt*16;
                uint32_t base = (uint32_t)(row << 7);
                uint32_t addr = aA + base + ((slo + ahi) ^ (((uint32_t)(row & 7)) << 4));
                ldm_x4(af[mt], addr);
            }
            #pragma unroll
            for (int p = 0; p < 2; ++p){
                int row = brow + p*16;
                uint32_t base = (uint32_t)(row << 7);
                uint32_t addr = aB + base + ((slo + bhi) ^ (((uint32_t)(row & 7)) << 4));
                uint32_t rr[4];
                ldm_x4(rr, addr);
                bf[2*p][0] = rr[0]; bf[2*p][1] = rr[1];
                bf[2*p+1][0] = rr[2]; bf[2*p+1][1] = rr[3];
            }
            #pragma unroll
            for (int mt = 0; mt < 4; ++mt)
            #pragma unroll
            for (int nt = 0; nt < 4; ++nt)
                mma_f16(acc[mt][nt], af[mt], bf[nt]);
        }
        // prefetch chunk c+2 into buffer (c+2)%3 == (c-1)%3 (safe: see sync above)
        if (c + 2 < nch) issue(c + 2);
        asm volatile("cp.async.commit_group;" ::: "memory");
    }

    const int rbase = m0 + wm*64 + (lid >> 2);
    const int cbase = n0 + wn*32 + (lid & 3)*2;
    if (!outHalf){
        float* C = (float*)Cv + (size_t)z * sC;
        #pragma unroll
        for (int mt = 0; mt < 4; ++mt)
        #pragma unroll
        for (int nt = 0; nt < 4; ++nt){
            int r0 = rbase + mt*16, cc = cbase + nt*8;
            *(float2*)(C + (size_t)r0 * ldc + cc)       = make_float2(acc[mt][nt][0], acc[mt][nt][1]);
            *(float2*)(C + (size_t)(r0+8) * ldc + cc)   = make_float2(acc[mt][nt][2], acc[mt][nt][3]);
        }
    } else {
        __half* C = (__half*)Cv + (size_t)z * sC;
        #pragma unroll
        for (int mt = 0; mt < 4; ++mt)
        #pragma unroll
        for (int nt = 0; nt < 4; ++nt){
            int r0 = rbase + mt*16, cc = cbase + nt*8;
            *(__half2*)(C + (size_t)r0 * ldc + cc)     = __floats2half2_rn(acc[mt][nt][0], acc[mt][nt][1]);
            *(__half2*)(C + (size_t)(r0+8) * ldc + cc) = __floats2half2_rn(acc[mt][nt][2], acc[mt][nt][3]);
        }
    }
}

// =====================================================================
// Prep / elementwise kernels
// =====================================================================
__global__ void k_prep_xA(const float2* __restrict__ x){
    int idx = blockIdx.x * 256 + threadIdx.x;      // 4096*1024
    int m = idx >> 10, ka = idx & 1023;
    float v = (ka < 512) ? x[(size_t)m*512 + ka].x : x[(size_t)m*512 + ka - 512].y;
    __half h, l; hsplit(v, h, l);
    size_t b = (size_t)m * 2048;
    gAq[b+ka] = h; gAq[b+1024+ka] = l;
}

__global__ void k_prep_qkvB(const float* __restrict__ wq_r, const float* __restrict__ wq_i,
                            const float* __restrict__ wkv_r, const float* __restrict__ wkv_i){
    int idx = blockIdx.x * 256 + threadIdx.x;      // 3072*1024
    int n = idx >> 10, k = idx & 1023;
    int ka = k & 511, isb = k >> 9;
    int im = n >= 1536;
    int c = im ? n - 1536 : n;
    const float* Wr = (c < 512) ? wq_r : wkv_r;
    const float* Wi = (c < 512) ? wq_i : wkv_i;
    int cc = (c < 512) ? c : c - 512;
    int ldw = (c < 512) ? 512 : 1024;
    float wr = Wr[(size_t)ka*ldw + cc], wi = Wi[(size_t)ka*ldw + cc];
    float v = im ? (isb ? wr : wi) : (isb ? -wi : wr);
    __half h = __float2half_rn(v);
    size_t b = (size_t)n * 2048;
    gBq[b+k] = h; gBq[b+1024+k] = h;
}

__global__ void k_prep_rel(const float* __restrict__ rel){
    int idx = blockIdx.x * 256 + threadIdx.x;
    if (idx < 1025*64) gBe[idx] = __float2half_rn(rel[idx]);
}

__global__ __launch_bounds__(256) void k_prep_attn(){
    __shared__ float sVr[64][65], sVi[64][65];
    const int bh = blockIdx.x, n0 = blockIdx.y << 6;
    const int b = bh >> 3, h = bh & 7;
    const int tid = threadIdx.x;
    const int dl = tid & 63;
    #pragma unroll
    for (int p = 0; p < 16; ++p){
        int nl = (p << 2) + (tid >> 6);
        int n = n0 + nl;
        size_t mrow = ((size_t)b*1024 + n) * 3072;
        int hd = h*64 + dl;
        float qr = gCq[mrow + hd],        qi = gCq[mrow + 1536 + hd];
        float kr = gCq[mrow + 512 + hd],  ki = gCq[mrow + 2048 + hd];
        float vr = gCq[mrow + 1024 + hd], vi = gCq[mrow + 2560 + hd];
        __half qh = __float2half_rn(qr);
        __half ih = __float2half_rn(qi);
        size_t ab = ((size_t)bh*1024 + n) * 128;
        gAs[ab+dl] = qh;     gAs[ab+64+dl] = ih;
        __half kh = __float2half_rn(kr);
        __half nh = __float2half_rn(-ki);
        __half kih = __float2half_rn(ki);
        size_t bb = ((size_t)bh*2048 + n) * 128;
        gBs[bb+dl] = kh;      gBs[bb+64+dl] = nh;
        size_t b2 = ((size_t)bh*2048 + 1024 + n) * 128;
        gBs[b2+dl] = kih;     gBs[b2+64+dl] = kh;
        gAe[((size_t)bh*2048 + n)*64 + dl] = qh;
        gAe[((size_t)bh*2048 + 1024 + n)*64 + dl] = ih;
        sVr[nl][dl] = vr; sVi[nl][dl] = vi;
    }
    __syncthreads();
    #pragma unroll
    for (int p = 0; p < 16; ++p){
        int d = (p << 2) + (tid >> 6);
        int n_ = tid & 63;
        __half h1 = __float2half_rn(sVr[n_][d]);
        __half h2 = __float2half_rn(sVi[n_][d]);
        size_t r1 = ((size_t)bh*128 + d)      * 2048 + n0 + n_;
        size_t r2 = ((size_t)bh*128 + 64 + d) * 2048 + n0 + n_;
        gBpv[r1] = h1; gBpv[r1+1024] = h1;
        gBpv[r2] = h2; gBpv[r2+1024] = h2;
    }
}

__global__ __launch_bounds__(256) void k_softmax(){
    int rowid = blockIdx.x * 8 + (threadIdx.x >> 5);
    int lane = threadIdx.x & 31;
    int bh = rowid >> 10, i = rowid & 1023;
    const __half* S = gS + ((size_t)bh*1024 + i) * 2048;
    const __half* Rr = gR + ((size_t)bh*2048 + i) * 1152;
    const __half* Ri = gR + ((size_t)bh*2048 + 1024 + i) * 1152;
    float mv[32], mx = -1e30f;
    #pragma unroll
    for (int t = 0; t < 32; ++t){
        int j = t*32 + lane;
        int u = i - j; u = u < -512 ? -512 : (u > 512 ? 512 : u); u += 512;
        float sr = __half2float(S[j])        + __half2float(Rr[u]);
        float si = __half2float(S[1024 + j]) + __half2float(Ri[u]);
        float m = 0.125f * sqrtf(sr*sr + si*si);
        mv[t] = m; mx = fmaxf(mx, m);
    }
    #pragma unroll
    for (int o = 16; o > 0; o >>= 1) mx = fmaxf(mx, __shfl_xor_sync(0xffffffffu, mx, o));
    float s = 0.f;
    #pragma unroll
    for (int t = 0; t < 32; ++t){ float e = __expf(mv[t] - mx); mv[t] = e; s += e; }
    #pragma unroll
    for (int o = 16; o > 0; o >>= 1) s += __shfl_xor_sync(0xffffffffu, s, o);
    float inv = 1.f / s;
    size_t pb = ((size_t)bh*1024 + i) * 2048;
    #pragma unroll
    for (int t = 0; t < 32; ++t){
        int j = t*32 + lane;
        __half h, l; hsplit(mv[t] * inv, h, l);
        gP[pb+j] = h; gP[pb+1024+j] = l;
    }
}

__global__ void k_prep_outA(){
    int idx = blockIdx.x * 256 + threadIdx.x;   // 4096*1024
    int m = idx >> 10, e = idx & 1023;
    int b = m >> 10, n = m & 1023;
    int eh = e & 511;
    int h = eh >> 6, d = eh & 63;
    float v = gCpv[(((size_t)(b*8 + h))*1024 + n)*128 + ((e >> 9) ? 64 : 0) + d];
    __half hh, ll; hsplit(v, hh, ll);
    size_t ab = (size_t)m * 2048;
    gAo[ab+e] = hh; gAo[ab+1024+e] = ll;
}

__global__ void k_prep_outB(const float* __restrict__ wo_r, const float* __restrict__ wo_i){
    int idx = blockIdx.x * 256 + threadIdx.x;   // 1024*1024
    int n = idx >> 10, k = idx & 1023;
    int c = n & 511, ka = k & 511;
    float wr = wo_r[(size_t)ka*512 + c], wi = wo_i[(size_t)ka*512 + c];
    float v = (n < 512) ? ((k < 512) ? wr : -wi) : ((k < 512) ? wi : wr);
    __half h = __float2half_rn(v);
    size_t bb = (size_t)n * 2048;
    gBo[bb+k] = h; gBo[bb+1024+k] = h;
}

__global__ void k_final(const float* __restrict__ bo_r, const float* __restrict__ bo_i,
                        float2* __restrict__ out){
    int idx = blockIdx.x * 256 + threadIdx.x;   // 4096*512
    int m = idx >> 9, c = idx & 511;
    out[(size_t)m*512 + c] = make_float2(gCo[(size_t)m*1024 + c]       + bo_r[c],
                                         gCo[(size_t)m*1024 + 512 + c] + bo_i[c]);
}

// =====================================================================
extern "C" void kernel_launch(void* const* d_in, const int* in_sizes, int n_in,
                              void* d_out, int out_size)
{
    const float2* x    = (const float2*)d_in[0];
    const float* wq_r  = (const float*)d_in[1];
    const float* wq_i  = (const float*)d_in[2];
    const float* wkv_r = (const float*)d_in[3];
    const float* wkv_i = (const float*)d_in[4];
    const float* wo_r  = (const float*)d_in[5];
    const float* wo_i  = (const float*)d_in[6];
    const float* bo_r  = (const float*)d_in[7];
    const float* bo_i  = (const float*)d_in[8];
    const float* rel   = (const float*)d_in[9];

    cudaFuncSetAttribute(k_gemm, cudaFuncAttributeMaxDynamicSharedMemorySize, GSMEM);

    void *pAq,*pBq,*pCq,*pAs,*pBs,*pS,*pAe,*pBe,*pR,*pP,*pBpv,*pCpv,*pAo,*pBo,*pCo;
    cudaGetSymbolAddress(&pAq, gAq);   cudaGetSymbolAddress(&pBq, gBq);
    cudaGetSymbolAddress(&pCq, gCq);   cudaGetSymbolAddress(&pAs, gAs);
    cudaGetSymbolAddress(&pBs, gBs);   cudaGetSymbolAddress(&pS,  gS);
    cudaGetSymbolAddress(&pAe, gAe);   cudaGetSymbolAddress(&pBe, gBe);
    cudaGetSymbolAddress(&pR,  gR);    cudaGetSymbolAddress(&pP,  gP);
    cudaGetSymbolAddress(&pBpv,gBpv);  cudaGetSymbolAddress(&pCpv,gCpv);
    cudaGetSymbolAddress(&pAo, gAo);   cudaGetSymbolAddress(&pBo, gBo);
    cudaGetSymbolAddress(&pCo, gCo);

    k_prep_xA  <<<16384, 256>>>(x);
    k_prep_qkvB<<<12288, 256>>>(wq_r, wq_i, wkv_r, wkv_i);
    k_prep_rel <<<257, 256>>>(rel);
    k_prep_outB<<<4096, 256>>>(wo_r, wo_i);

    // QKV: C[4096,3072] = A[4096,2048] * B[3072,2048]^T
    k_gemm<<<dim3(32,24,1), 256, GSMEM>>>((__half*)pAq, (__half*)pBq, pCq,
        2048, 3072, 0LL, 0LL, 0LL, 0);
    k_prep_attn<<<dim3(32,16), 256>>>();
    // S: per bh, [1024,2048] = A[1024,128]*B[2048,128]^T, fp16 out
    k_gemm<<<dim3(8,16,32), 256, GSMEM>>>((__half*)pAs, (__half*)pBs, pS,
        128, 2048, 1024LL*128, 2048LL*128, 1024LL*2048, 1);
    // REL: per bh, [2048,1152] = A[2048,64]*B[1152,64]^T (B broadcast), fp16 out
    k_gemm<<<dim3(16,9,32), 256, GSMEM>>>((__half*)pAe, (__half*)pBe, pR,
        64, 1152, 2048LL*64, 0LL, 2048LL*1152, 1);
    k_softmax<<<4096, 256>>>();
    // PV: per bh, [1024,128] = P[1024,2048]*V[128,2048]^T
    k_gemm<<<dim3(8,1,32), 256, GSMEM>>>((__half*)pP, (__half*)pBpv, pCpv,
        2048, 128, 1024LL*2048, 128LL*2048, 1024LL*128, 0);
    k_prep_outA<<<16384, 256>>>();
    // OUT: [4096,1024] = A[4096,2048]*B[1024,2048]^T
    k_gemm<<<dim3(32,8,1), 256, GSMEM>>>((__half*)pAo, (__half*)pBo, pCo,
        2048, 1024, 0LL, 0LL, 0LL, 0);
    k_final<<<8192, 256>>>(bo_r, bo_i, (float2*)d_out);
}

// round 15
// speedup vs baseline: 1.4015x; 1.4015x over previous
#include <cuda_runtime.h>
#include <cuda_bf16.h>
#include <cuda_fp16.h>
#include <stdint.h>
#include <math.h>

// ---------------- scratch (__device__ globals; allocation-free) ----------------
__device__ __half gAq[(size_t)4096*2048];
__device__ __half gBq[(size_t)3072*2048];
__device__ float  gCq[(size_t)4096*3072];
__device__ __half gAs[(size_t)32*1024*128];
__device__ __half gBs[(size_t)32*2048*128];
__device__ __half gS [(size_t)32*1024*2048];
__device__ __half gAe[(size_t)32*2048*64];
__device__ __half gBe[(size_t)1152*64];        // rows >=1025 stay zero
__device__ __half gR [(size_t)32*2048*1152];
__device__ __half gP [(size_t)32*1024*2048];
__device__ __half gBpv[(size_t)32*128*2048];
__device__ float  gCpv[(size_t)32*1024*128];
__device__ __half gAo[(size_t)4096*2048];
__device__ __half gBo[(size_t)1024*2048];
__device__ float  gCo[(size_t)4096*1024];

// ---------------- helpers ----------------
__device__ __forceinline__ uint32_t smem_u32(const void* p){
    uint32_t a;
    asm("{ .reg .u64 t; cvta.to.shared.u64 t, %1; cvt.u32.u64 %0, t; }" : "=r"(a) : "l"(p));
    return a;
}
__device__ __forceinline__ void hsplit(float v, __half& h, __half& l){
    h = __float2half_rn(v);
    l = __float2half_rn(v - __half2float(h));
}
__device__ __forceinline__ void ldm_x4(uint32_t* r, uint32_t addr){
    asm volatile("ldmatrix.sync.aligned.m8n8.x4.shared.b16 {%0,%1,%2,%3}, [%4];"
                 : "=r"(r[0]), "=r"(r[1]), "=r"(r[2]), "=r"(r[3]) : "r"(addr));
}
__device__ __forceinline__ void mma_f16(float* c, const uint32_t* a, const uint32_t* b){
    asm volatile(
        "mma.sync.aligned.m16n8k16.row.col.f32.f16.f16.f32 "
        "{%0,%1,%2,%3}, {%4,%5,%6,%7}, {%8,%9}, {%0,%1,%2,%3};"
        : "+f"(c[0]), "+f"(c[1]), "+f"(c[2]), "+f"(c[3])
        : "r"(a[0]), "r"(a[1]), "r"(a[2]), "r"(a[3]), "r"(b[0]), "r"(b[1]));
}
__device__ __forceinline__ void cp16(uint32_t saddr, const void* gptr){
    asm volatile("cp.async.cg.shared.global [%0], [%1], 16;"
                 :: "r"(saddr), "l"(gptr) : "memory");
}

// =====================================================================
// Generic batched GEMM: C[z][M][N] = A[z][M][K] * B[z][N][K]^T
// fp16 in (K-major), fp32 accum via HMMA m16n8k16; C fp32 or fp16.
// Tile 128x128, K-chunk 64, 3-stage cp.async pipeline (R9 structure).
// =====================================================================
#define GSMEM (3*32768 + 1024)
__global__ __launch_bounds__(256, 2) void k_gemm(
    const __half* __restrict__ A, const __half* __restrict__ B, void* __restrict__ Cv,
    int K, int ldc, long long sA, long long sB, long long sC, int outHalf)
{
    extern __shared__ char smraw[];
    const uint32_t aBase = (smem_u32(smraw) + 1023u) & ~1023u;
    const int tid = threadIdx.x, wid = tid >> 5, lid = tid & 31;
    const int wm = wid & 1, wn = wid >> 1;           // 2 x 4 warp grid
    const int m0 = blockIdx.x << 7, n0 = blockIdx.y << 7, z = blockIdx.z;
    A += (size_t)z * (size_t)sA;
    B += (size_t)z * (size_t)sB;

    float acc[4][4][4];
    #pragma unroll
    for (int i = 0; i < 4; ++i)
    #pragma unroll
    for (int j = 0; j < 4; ++j)
    #pragma unroll
    for (int k = 0; k < 4; ++k) acc[i][j][k] = 0.f;

    // A: row = wm*64 + mt*16 + (lid&15); k-unit(16B) = s*2 + (lid>>4)
    const int arow = wm*64 + (lid & 15);
    const uint32_t ahi = (uint32_t)(lid >> 4) << 4;           // 0 or 16 bytes
    // B: row = wn*32 + (2p + (g>>1))*8 + (lid&7); unit = s*2 + (g&1)
    const int g = lid >> 3;
    const int brow = wn*32 + ((g >> 1) << 3) + (lid & 7);
    const uint32_t bhi = (uint32_t)(g & 1) << 4;

    const int nch = K >> 6, kq = K >> 3;
    const int lr = tid >> 3, lq = tid & 7;

    auto issue = [&](int cidx){
        const int st = cidx - (cidx/3)*3;
        const uint32_t dA = aBase + (uint32_t)st * 32768u;
        const uint32_t dB = dA + 16384u;
        const uint4* a4 = (const uint4*)(A + (size_t)m0 * K) + cidx * 8;
        const uint4* b4 = (const uint4*)(B + (size_t)n0 * K) + cidx * 8;
        #pragma unroll
        for (int it = 0; it < 4; ++it){
            int r = lr + it*32;
            uint32_t off = (uint32_t)((r << 7) | (lq << 4));
            uint32_t sw = off ^ ((off >> 3) & 0x70);
            cp16(dA + sw, a4 + (size_t)r * kq + lq);
            cp16(dB + sw, b4 + (size_t)r * kq + lq);
        }
    };

    if (0 < nch) issue(0);
    asm volatile("cp.async.commit_group;" ::: "memory");
    if (1 < nch) issue(1);
    asm volatile("cp.async.commit_group;" ::: "memory");

    for (int c = 0; c < nch; ++c){
        if (c + 2 < nch) issue(c + 2);
        asm volatile("cp.async.commit_group;" ::: "memory");
        asm volatile("cp.async.wait_group %0;" :: "n"(2));
        __syncthreads();

        const int st = c - (c/3)*3;
        const uint32_t aA = aBase + (uint32_t)st * 32768u;
        const uint32_t aB = aA + 16384u;
        #pragma unroll
        for (int s = 0; s < 4; ++s){
            const uint32_t slo = (uint32_t)s << 5;            // s*32 bytes
            uint32_t af[4][4], bf[4][2];
            #pragma unroll
            for (int mt = 0; mt < 4; ++mt){
                int row = arow + mt*16;
                uint32_t base = (uint32_t)(row << 7);
                uint32_t addr = aA + base + ((slo + ahi) ^ (((uint32_t)(row & 7)) << 4));
                ldm_x4(af[mt], addr);
            }
            #pragma unroll
            for (int p = 0; p < 2; ++p){
                int row = brow + p*16;
                uint32_t base = (uint32_t)(row << 7);
                uint32_t addr = aB + base + ((slo + bhi) ^ (((uint32_t)(row & 7)) << 4));
                uint32_t rr[4];
                ldm_x4(rr, addr);
                bf[2*p][0] = rr[0]; bf[2*p][1] = rr[1];
                bf[2*p+1][0] = rr[2]; bf[2*p+1][1] = rr[3];
            }
            #pragma unroll
            for (int mt = 0; mt < 4; ++mt)
            #pragma unroll
            for (int nt = 0; nt < 4; ++nt)
                mma_f16(acc[mt][nt], af[mt], bf[nt]);
        }
        __syncthreads();
    }

    const int rbase = m0 + wm*64 + (lid >> 2);
    const int cbase = n0 + wn*32 + (lid & 3)*2;
    if (!outHalf){
        float* C = (float*)Cv + (size_t)z * sC;
        #pragma unroll
        for (int mt = 0; mt < 4; ++mt)
        #pragma unroll
        for (int nt = 0; nt < 4; ++nt){
            int r0 = rbase + mt*16, cc = cbase + nt*8;
            *(float2*)(C + (size_t)r0 * ldc + cc)       = make_float2(acc[mt][nt][0], acc[mt][nt][1]);
            *(float2*)(C + (size_t)(r0+8) * ldc + cc)   = make_float2(acc[mt][nt][2], acc[mt][nt][3]);
        }
    } else {
        __half* C = (__half*)Cv + (size_t)z * sC;
        #pragma unroll
        for (int mt = 0; mt < 4; ++mt)
        #pragma unroll
        for (int nt = 0; nt < 4; ++nt){
            int r0 = rbase + mt*16, cc = cbase + nt*8;
            *(__half2*)(C + (size_t)r0 * ldc + cc)     = __floats2half2_rn(acc[mt][nt][0], acc[mt][nt][1]);
            *(__half2*)(C + (size_t)(r0+8) * ldc + cc) = __floats2half2_rn(acc[mt][nt][2], acc[mt][nt][3]);
        }
    }
}

// =====================================================================
// Prep / elementwise kernels
// =====================================================================
__global__ void k_prep_xA(const float2* __restrict__ x){
    int idx = blockIdx.x * 256 + threadIdx.x;      // 4096*1024
    int m = idx >> 10, ka = idx & 1023;
    float v = (ka < 512) ? x[(size_t)m*512 + ka].x : x[(size_t)m*512 + ka - 512].y;
    __half h, l; hsplit(v, h, l);
    size_t b = (size_t)m * 2048;
    gAq[b+ka] = h; gAq[b+1024+ka] = l;
}

__global__ void k_prep_qkvB(const float* __restrict__ wq_r, const float* __restrict__ wq_i,
                            const float* __restrict__ wkv_r, const float* __restrict__ wkv_i){
    int idx = blockIdx.x * 256 + threadIdx.x;      // 3072*1024
    int n = idx >> 10, k = idx & 1023;
    int ka = k & 511, isb = k >> 9;
    int im = n >= 1536;
    int c = im ? n - 1536 : n;
    const float* Wr = (c < 512) ? wq_r : wkv_r;
    const float* Wi = (c < 512) ? wq_i : wkv_i;
    int cc = (c < 512) ? c : c - 512;
    int ldw = (c < 512) ? 512 : 1024;
    float wr = Wr[(size_t)ka*ldw + cc], wi = Wi[(size_t)ka*ldw + cc];
    float v = im ? (isb ? wr : wi) : (isb ? -wi : wr);
    __half h = __float2half_rn(v);
    size_t b = (size_t)n * 2048;
    gBq[b+k] = h; gBq[b+1024+k] = h;
}

__global__ void k_prep_rel(const float* __restrict__ rel){
    int idx = blockIdx.x * 256 + threadIdx.x;
    if (idx < 1025*64) gBe[idx] = __float2half_rn(rel[idx]);
}

__global__ __launch_bounds__(256) void k_prep_attn(){
    __shared__ float sVr[64][65], sVi[64][65];
    const int bh = blockIdx.x, n0 = blockIdx.y << 6;
    const int b = bh >> 3, h = bh & 7;
    const int tid = threadIdx.x;
    const int dl = tid & 63;
    #pragma unroll
    for (int p = 0; p < 16; ++p){
        int nl = (p << 2) + (tid >> 6);
        int n = n0 + nl;
        size_t mrow = ((size_t)b*1024 + n) * 3072;
        int hd = h*64 + dl;
        float qr = gCq[mrow + hd],        qi = gCq[mrow + 1536 + hd];
        float kr = gCq[mrow + 512 + hd],  ki = gCq[mrow + 2048 + hd];
        float vr = gCq[mrow + 1024 + hd], vi = gCq[mrow + 2560 + hd];
        __half qh = __float2half_rn(qr);
        __half ih = __float2half_rn(qi);
        size_t ab = ((size_t)bh*1024 + n) * 128;
        gAs[ab+dl] = qh;     gAs[ab+64+dl] = ih;
        __half kh = __float2half_rn(kr);
        __half nh = __float2half_rn(-ki);
        __half kih = __float2half_rn(ki);
        size_t bb = ((size_t)bh*2048 + n) * 128;
        gBs[bb+dl] = kh;      gBs[bb+64+dl] = nh;
        size_t b2 = ((size_t)bh*2048 + 1024 + n) * 128;
        gBs[b2+dl] = kih;     gBs[b2+64+dl] = kh;
        gAe[((size_t)bh*2048 + n)*64 + dl] = qh;
        gAe[((size_t)bh*2048 + 1024 + n)*64 + dl] = ih;
        sVr[nl][dl] = vr; sVi[nl][dl] = vi;
    }
    __syncthreads();
    #pragma unroll
    for (int p = 0; p < 16; ++p){
        int d = (p << 2) + (tid >> 6);
        int n_ = tid & 63;
        __half h1 = __float2half_rn(sVr[n_][d]);
        __half h2 = __float2half_rn(sVi[n_][d]);
        size_t r1 = ((size_t)bh*128 + d)      * 2048 + n0 + n_;
        size_t r2 = ((size_t)bh*128 + 64 + d) * 2048 + n0 + n_;
        gBpv[r1] = h1; gBpv[r1+1024] = h1;
        gBpv[r2] = h2; gBpv[r2+1024] = h2;
    }
}

__global__ __launch_bounds__(256) void k_softmax(){
    int rowid = blockIdx.x * 8 + (threadIdx.x >> 5);
    int lane = threadIdx.x & 31;
    int bh = rowid >> 10, i = rowid & 1023;
    const __half* S = gS + ((size_t)bh*1024 + i) * 2048;
    const __half* Rr = gR + ((size_t)bh*2048 + i) * 1152;
    const __half* Ri = gR + ((size_t)bh*2048 + 1024 + i) * 1152;
    float mv[32], mx = -1e30f;
    #pragma unroll
    for (int t = 0; t < 32; ++t){
        int j = t*32 + lane;
        int u = i - j; u = u < -512 ? -512 : (u > 512 ? 512 : u); u += 512;
        float sr = __half2float(S[j])        + __half2float(Rr[u]);
        float si = __half2float(S[1024 + j]) + __half2float(Ri[u]);
        float m = 0.125f * sqrtf(sr*sr + si*si);
        mv[t] = m; mx = fmaxf(mx, m);
    }
    #pragma unroll
    for (int o = 16; o > 0; o >>= 1) mx = fmaxf(mx, __shfl_xor_sync(0xffffffffu, mx, o));
    float s = 0.f;
    #pragma unroll
    for (int t = 0; t < 32; ++t){ float e = __expf(mv[t] - mx); mv[t] = e; s += e; }
    #pragma unroll
    for (int o = 16; o > 0; o >>= 1) s += __shfl_xor_sync(0xffffffffu, s, o);
    float inv = 1.f / s;
    size_t pb = ((size_t)bh*1024 + i) * 2048;
    #pragma unroll
    for (int t = 0; t < 32; ++t){
        int j = t*32 + lane;
        __half h, l; hsplit(mv[t] * inv, h, l);
        gP[pb+j] = h; gP[pb+1024+j] = l;
    }
}

__global__ void k_prep_outA(){
    int idx = blockIdx.x * 256 + threadIdx.x;   // 4096*1024
    int m = idx >> 10, e = idx & 1023;
    int b = m >> 10, n = m & 1023;
    int eh = e & 511;
    int h = eh >> 6, d = eh & 63;
    float v = gCpv[(((size_t)(b*8 + h))*1024 + n)*128 + ((e >> 9) ? 64 : 0) + d];
    __half hh, ll; hsplit(v, hh, ll);
    size_t ab = (size_t)m * 2048;
    gAo[ab+e] = hh; gAo[ab+1024+e] = ll;
}

__global__ void k_prep_outB(const float* __restrict__ wo_r, const float* __restrict__ wo_i){
    int idx = blockIdx.x * 256 + threadIdx.x;   // 1024*1024
    int n = idx >> 10, k = idx & 1023;
    int c = n & 511, ka = k & 511;
    float wr = wo_r[(size_t)ka*512 + c], wi = wo_i[(size_t)ka*512 + c];
    float v = (n < 512) ? ((k < 512) ? wr : -wi) : ((k < 512) ? wi : wr);
    __half h = __float2half_rn(v);
    size_t bb = (size_t)n * 2048;
    gBo[bb+k] = h; gBo[bb+1024+k] = h;
}

__global__ void k_final(const float* __restrict__ bo_r, const float* __restrict__ bo_i,
                        float2* __restrict__ out){
    int idx = blockIdx.x * 256 + threadIdx.x;   // 4096*512
    int m = idx >> 9, c = idx & 511;
    out[(size_t)m*512 + c] = make_float2(gCo[(size_t)m*1024 + c]       + bo_r[c],
                                         gCo[(size_t)m*1024 + 512 + c] + bo_i[c]);
}

// =====================================================================
extern "C" void kernel_launch(void* const* d_in, const int* in_sizes, int n_in,
                              void* d_out, int out_size)
{
    const float2* x    = (const float2*)d_in[0];
    const float* wq_r  = (const float*)d_in[1];
    const float* wq_i  = (const float*)d_in[2];
    const float* wkv_r = (const float*)d_in[3];
    const float* wkv_i = (const float*)d_in[4];
    const float* wo_r  = (const float*)d_in[5];
    const float* wo_i  = (const float*)d_in[6];
    const float* bo_r  = (const float*)d_in[7];
    const float* bo_i  = (const float*)d_in[8];
    const float* rel   = (const float*)d_in[9];

    cudaFuncSetAttribute(k_gemm, cudaFuncAttributeMaxDynamicSharedMemorySize, GSMEM);

    void *pAq,*pBq,*pCq,*pAs,*pBs,*pS,*pAe,*pBe,*pR,*pP,*pBpv,*pCpv,*pAo,*pBo,*pCo;
    cudaGetSymbolAddress(&pAq, gAq);   cudaGetSymbolAddress(&pBq, gBq);
    cudaGetSymbolAddress(&pCq, gCq);   cudaGetSymbolAddress(&pAs, gAs);
    cudaGetSymbolAddress(&pBs, gBs);   cudaGetSymbolAddress(&pS,  gS);
    cudaGetSymbolAddress(&pAe, gAe);   cudaGetSymbolAddress(&pBe, gBe);
    cudaGetSymbolAddress(&pR,  gR);    cudaGetSymbolAddress(&pP,  gP);
    cudaGetSymbolAddress(&pBpv,gBpv);  cudaGetSymbolAddress(&pCpv,gCpv);
    cudaGetSymbolAddress(&pAo, gAo);   cudaGetSymbolAddress(&pBo, gBo);
    cudaGetSymbolAddress(&pCo, gCo);

    k_prep_xA  <<<16384, 256>>>(x);
    k_prep_qkvB<<<12288, 256>>>(wq_r, wq_i, wkv_r, wkv_i);
    k_prep_rel <<<257, 256>>>(rel);
    k_prep_outB<<<4096, 256>>>(wo_r, wo_i);

    // QKV: C[4096,3072] = A[4096,2048] * B[3072,2048]^T
    k_gemm<<<dim3(32,24,1), 256, GSMEM>>>((__half*)pAq, (__half*)pBq, pCq,
        2048, 3072, 0LL, 0LL, 0LL, 0);
    k_prep_attn<<<dim3(32,16), 256>>>();
    // S: per bh, [1024,2048] = A[1024,128]*B[2048,128]^T, fp16 out
    k_gemm<<<dim3(8,16,32), 256, GSMEM>>>((__half*)pAs, (__half*)pBs, pS,
        128, 2048, 1024LL*128, 2048LL*128, 1024LL*2048, 1);
    // REL: per bh, [2048,1152] = A[2048,64]*B[1152,64]^T (B broadcast), fp16 out
    k_gemm<<<dim3(16,9,32), 256, GSMEM>>>((__half*)pAe, (__half*)pBe, pR,
        64, 1152, 2048LL*64, 0LL, 2048LL*1152, 1);
    k_softmax<<<4096, 256>>>();
    // PV: per bh, [1024,128] = P[1024,2048]*V[128,2048]^T
    k_gemm<<<dim3(8,1,32), 256, GSMEM>>>((__half*)pP, (__half*)pBpv, pCpv,
        2048, 128, 1024LL*2048, 128LL*2048, 1024LL*128, 0);
    k_prep_outA<<<16384, 256>>>();
    // OUT: [4096,1024] = A[4096,2048]*B[1024,2048]^T
    k_gemm<<<dim3(32,8,1), 256, GSMEM>>>((__half*)pAo, (__half*)pBo, pCo,
        2048, 1024, 0LL, 0LL, 0LL, 0);
    k_final<<<8192, 256>>>(bo_r, bo_i, (float2*)d_out);
}

// round 17
// speedup vs baseline: 1.6455x; 1.1741x over previous
#include <cuda_runtime.h>
#include <cuda_bf16.h>
#include <cuda_fp16.h>
#include <stdint.h>
#include <math.h>

// ---------------- scratch (__device__ globals; allocation-free) ----------------
__device__ __half gAq[(size_t)4096*2048];
__device__ __half gBq[(size_t)3072*2048];
__device__ float  gCq[(size_t)4096*3072];
__device__ __half gQf[(size_t)32*1024*128];   // [bh][n][qr(0:64)|qi(64:128)]
__device__ __half gKf[(size_t)32*1024*128];   // [bh][n][kr|-ki]
__device__ __half gVf[(size_t)32*128*1024];   // [bh][vr d0..63, vi d0..63][n]
__device__ __half gBe[(size_t)1152*64];       // rel fp16; rows >=1025 unused
__device__ __half gAo[(size_t)4096*2048];
__device__ __half gBo[(size_t)1024*2048];
__device__ float  gCo[(size_t)4096*1024];

// ---------------- helpers ----------------
__device__ __forceinline__ uint32_t smem_u32(const void* p){
    uint32_t a;
    asm("{ .reg .u64 t; cvta.to.shared.u64 t, %1; cvt.u32.u64 %0, t; }" : "=r"(a) : "l"(p));
    return a;
}
__device__ __forceinline__ void hsplit(float v, __half& h, __half& l){
    h = __float2half_rn(v);
    l = __float2half_rn(v - __half2float(h));
}
__device__ __forceinline__ void ldm_x4(uint32_t* r, uint32_t addr){
    asm volatile("ldmatrix.sync.aligned.m8n8.x4.shared.b16 {%0,%1,%2,%3}, [%4];"
                 : "=r"(r[0]), "=r"(r[1]), "=r"(r[2]), "=r"(r[3]) : "r"(addr));
}
__device__ __forceinline__ void mma_f16(float* c, const uint32_t* a, const uint32_t* b){
    asm volatile(
        "mma.sync.aligned.m16n8k16.row.col.f32.f16.f16.f32 "
        "{%0,%1,%2,%3}, {%4,%5,%6,%7}, {%8,%9}, {%0,%1,%2,%3};"
        : "+f"(c[0]), "+f"(c[1]), "+f"(c[2]), "+f"(c[3])
        : "r"(a[0]), "r"(a[1]), "r"(a[2]), "r"(a[3]), "r"(b[0]), "r"(b[1]));
}
__device__ __forceinline__ void cp16(uint32_t saddr, const void* gptr){
    asm volatile("cp.async.cg.shared.global [%0], [%1], 16;"
                 :: "r"(saddr), "l"(gptr) : "memory");
}

// =====================================================================
// Generic batched GEMM (unchanged R15 winner): C = A * B^T, HMMA fp16.
// =====================================================================
#define GSMEM (3*32768 + 1024)
__global__ __launch_bounds__(256, 2) void k_gemm(
    const __half* __restrict__ A, const __half* __restrict__ B, void* __restrict__ Cv,
    int K, int ldc, long long sA, long long sB, long long sC, int outHalf)
{
    extern __shared__ char smraw[];
    const uint32_t aBase = (smem_u32(smraw) + 1023u) & ~1023u;
    const int tid = threadIdx.x, wid = tid >> 5, lid = tid & 31;
    const int wm = wid & 1, wn = wid >> 1;
    const int m0 = blockIdx.x << 7, n0 = blockIdx.y << 7, z = blockIdx.z;
    A += (size_t)z * (size_t)sA;
    B += (size_t)z * (size_t)sB;

    float acc[4][4][4];
    #pragma unroll
    for (int i = 0; i < 4; ++i)
    #pragma unroll
    for (int j = 0; j < 4; ++j)
    #pragma unroll
    for (int k = 0; k < 4; ++k) acc[i][j][k] = 0.f;

    const int arow = wm*64 + (lid & 15);
    const uint32_t ahi = (uint32_t)(lid >> 4) << 4;
    const int g = lid >> 3;
    const int brow = wn*32 + ((g >> 1) << 3) + (lid & 7);
    const uint32_t bhi = (uint32_t)(g & 1) << 4;

    const int nch = K >> 6, kq = K >> 3;
    const int lr = tid >> 3, lq = tid & 7;

    auto issue = [&](int cidx){
        const int st = cidx - (cidx/3)*3;
        const uint32_t dA = aBase + (uint32_t)st * 32768u;
        const uint32_t dB = dA + 16384u;
        const uint4* a4 = (const uint4*)(A + (size_t)m0 * K) + cidx * 8;
        const uint4* b4 = (const uint4*)(B + (size_t)n0 * K) + cidx * 8;
        #pragma unroll
        for (int it = 0; it < 4; ++it){
            int r = lr + it*32;
            uint32_t off = (uint32_t)((r << 7) | (lq << 4));
            uint32_t sw = off ^ ((off >> 3) & 0x70);
            cp16(dA + sw, a4 + (size_t)r * kq + lq);
            cp16(dB + sw, b4 + (size_t)r * kq + lq);
        }
    };

    if (0 < nch) issue(0);
    asm volatile("cp.async.commit_group;" ::: "memory");
    if (1 < nch) issue(1);
    asm volatile("cp.async.commit_group;" ::: "memory");

    for (int c = 0; c < nch; ++c){
        if (c + 2 < nch) issue(c + 2);
        asm volatile("cp.async.commit_group;" ::: "memory");
        asm volatile("cp.async.wait_group %0;" :: "n"(2));
        __syncthreads();

        const int st = c - (c/3)*3;
        const uint32_t aA = aBase + (uint32_t)st * 32768u;
        const uint32_t aB = aA + 16384u;
        #pragma unroll
        for (int s = 0; s < 4; ++s){
            const uint32_t slo = (uint32_t)s << 5;
            uint32_t af[4][4], bf[4][2];
            #pragma unroll
            for (int mt = 0; mt < 4; ++mt){
                int row = arow + mt*16;
                uint32_t base = (uint32_t)(row << 7);
                uint32_t addr = aA + base + ((slo + ahi) ^ (((uint32_t)(row & 7)) << 4));
                ldm_x4(af[mt], addr);
            }
            #pragma unroll
            for (int p = 0; p < 2; ++p){
                int row = brow + p*16;
                uint32_t base = (uint32_t)(row << 7);
                uint32_t addr = aB + base + ((slo + bhi) ^ (((uint32_t)(row & 7)) << 4));
                uint32_t rr[4];
                ldm_x4(rr, addr);
                bf[2*p][0] = rr[0]; bf[2*p][1] = rr[1];
                bf[2*p+1][0] = rr[2]; bf[2*p+1][1] = rr[3];
            }
            #pragma unroll
            for (int mt = 0; mt < 4; ++mt)
            #pragma unroll
            for (int nt = 0; nt < 4; ++nt)
                mma_f16(acc[mt][nt], af[mt], bf[nt]);
        }
        __syncthreads();
    }

    const int rbase = m0 + wm*64 + (lid >> 2);
    const int cbase = n0 + wn*32 + (lid & 3)*2;
    if (!outHalf){
        float* C = (float*)Cv + (size_t)z * sC;
        #pragma unroll
        for (int mt = 0; mt < 4; ++mt)
        #pragma unroll
        for (int nt = 0; nt < 4; ++nt){
            int r0 = rbase + mt*16, cc = cbase + nt*8;
            *(float2*)(C + (size_t)r0 * ldc + cc)       = make_float2(acc[mt][nt][0], acc[mt][nt][1]);
            *(float2*)(C + (size_t)(r0+8) * ldc + cc)   = make_float2(acc[mt][nt][2], acc[mt][nt][3]);
        }
    } else {
        __half* C = (__half*)Cv + (size_t)z * sC;
        #pragma unroll
        for (int mt = 0; mt < 4; ++mt)
        #pragma unroll
        for (int nt = 0; nt < 4; ++nt){
            int r0 = rbase + mt*16, cc = cbase + nt*8;
            *(__half2*)(C + (size_t)r0 * ldc + cc)     = __floats2half2_rn(acc[mt][nt][0], acc[mt][nt][1]);
            *(__half2*)(C + (size_t)(r0+8) * ldc + cc) = __floats2half2_rn(acc[mt][nt][2], acc[mt][nt][3]);
        }
    }
}

// =====================================================================
// Fused attention: per CTA one (bh, 128-row q tile); loop 8 key tiles.
// smem byte offsets (padded pitches, no swizzle):
//  Q 0 (128x272B)  K 34816  V 69632  REL 104448 (256x144B)  E 141312 (128x528B)
//  floats @208896: mRow128 lRow128 aRow128 sRed512
// =====================================================================
#define FSMEM 212992
__global__ __launch_bounds__(256, 1) void k_attn_fused(
    const __half* __restrict__ Qf, const __half* __restrict__ Kf,
    const __half* __restrict__ Vf, const __half* __restrict__ Rel,
    __half* __restrict__ Ao)
{
    extern __shared__ char smraw[];
    const uint32_t base = smem_u32(smraw);
    __half* smh = (__half*)smraw;
    float* fl   = (float*)(smraw + 208896);
    float* mRow = fl;
    float* lRow = fl + 128;
    float* aRow = fl + 256;
    float* sRed = fl + 384;

    const int tid = threadIdx.x, wid = tid >> 5, lid = tid & 31;
    const int wm = wid & 1, wc = wid >> 1;
    const int g = lid >> 3;
    const int bh = blockIdx.x, i0 = blockIdx.y << 7;

    const char* Qp = (const char*)(Qf + ((size_t)bh*1024 + i0) * 128);
    const char* Kp = (const char*)(Kf + (size_t)bh*1024*128);
    const char* Vp = (const char*)(Vf + (size_t)bh*128*1024);

    // load Q once (128 rows x 256B -> pitch 272B)
    #pragma unroll
    for (int it = 0; it < 8; ++it){
        int cid = it*256 + tid, r = cid >> 4, q = cid & 15;
        cp16(base + (uint32_t)(r*272 + q*16), Qp + r*256 + q*16);
    }
    asm volatile("cp.async.commit_group;" ::: "memory");

    if (tid < 128){ mRow[tid] = -1e30f; lRow[tid] = 0.f; }

    float O[4][4][4];
    #pragma unroll
    for (int a = 0; a < 4; ++a)
    #pragma unroll
    for (int b2 = 0; b2 < 4; ++b2)
    #pragma unroll
    for (int c = 0; c < 4; ++c) O[a][b2][c] = 0.f;

    // E GEMM: [128 x 256] = A(q half, K=64) * RelWin^T, fp16 out to E region
    auto egemm = [&](int akoff){
        #pragma unroll
        for (int hh = 0; hh < 2; ++hh){
            float e[4][4][4];
            #pragma unroll
            for (int a = 0; a < 4; ++a)
            #pragma unroll
            for (int b2 = 0; b2 < 4; ++b2)
            #pragma unroll
            for (int c = 0; c < 4; ++c) e[a][b2][c] = 0.f;
            #pragma unroll
            for (int s = 0; s < 4; ++s){
                uint32_t af[4][4], bf[4][2];
                #pragma unroll
                for (int mt = 0; mt < 4; ++mt){
                    int arow = wm*64 + mt*16 + (lid & 15);
                    ldm_x4(af[mt], base + (uint32_t)(arow*272 + akoff + s*32 + ((lid>>4)<<4)));
                }
                #pragma unroll
                for (int p = 0; p < 2; ++p){
                    int brow = hh*128 + wc*32 + ((g>>1)<<3) + (lid & 7) + p*16;
                    uint32_t rr[4];
                    ldm_x4(rr, base + 104448u + (uint32_t)(brow*144 + s*32 + ((g&1)<<4)));
                    bf[2*p][0] = rr[0]; bf[2*p][1] = rr[1];
                    bf[2*p+1][0] = rr[2]; bf[2*p+1][1] = rr[3];
                }
                #pragma unroll
                for (int mt = 0; mt < 4; ++mt)
                #pragma unroll
                for (int nt = 0; nt < 4; ++nt)
                    mma_f16(e[mt][nt], af[mt], bf[nt]);
            }
            #pragma unroll
            for (int mt = 0; mt < 4; ++mt)
            #pragma unroll
            for (int nt = 0; nt < 4; ++nt){
                int r0 = wm*64 + mt*16 + (lid>>2);
                int c0 = hh*128 + wc*32 + nt*8 + (lid&3)*2;
                *(__half2*)(smh + 70656 + r0*264 + c0)     = __floats2half2_rn(e[mt][nt][0], e[mt][nt][1]);
                *(__half2*)(smh + 70656 + (r0+8)*264 + c0) = __floats2half2_rn(e[mt][nt][2], e[mt][nt][3]);
            }
        }
    };

    for (int jt = 0; jt < 8; ++jt){
        const int j0 = jt << 7;
        // load K tile
        #pragma unroll
        for (int it = 0; it < 8; ++it){
            int cid = it*256 + tid, r = cid >> 4, q = cid & 15;
            cp16(base + 34816u + (uint32_t)(r*272 + q*16), Kp + (size_t)(j0 + r)*256 + q*16);
        }
        // load V tile (rows = v-dims, cols = keys j0..j0+127)
        #pragma unroll
        for (int it = 0; it < 8; ++it){
            int cid = it*256 + tid, d = cid >> 4, q = cid & 15;
            cp16(base + 69632u + (uint32_t)(d*272 + q*16), Vp + (size_t)d*2048 + j0*2 + q*16);
        }
        // load rel window (clamped source rows)
        const int u0 = i0 - j0 + 385;
        #pragma unroll
        for (int it = 0; it < 8; ++it){
            int cid = it*256 + tid, r = cid >> 3, q = cid & 7;
            int src = u0 + r; src = src < 0 ? 0 : (src > 1024 ? 1024 : src);
            cp16(base + 104448u + (uint32_t)(r*144 + q*16), (const char*)Rel + (size_t)src*128 + q*16);
        }
        asm volatile("cp.async.commit_group;" ::: "memory");
        asm volatile("cp.async.wait_group 0;" ::: "memory");
        __syncthreads();

        // ---- Er -> sE ----
        egemm(0);
        __syncthreads();

        // ---- Sr = sQ * sK^T (K=128), gather Er ----
        float sr[4][4][4];
        #pragma unroll
        for (int a = 0; a < 4; ++a)
        #pragma unroll
        for (int b2 = 0; b2 < 4; ++b2)
        #pragma unroll
        for (int c = 0; c < 4; ++c) sr[a][b2][c] = 0.f;
        #pragma unroll
        for (int s = 0; s < 8; ++s){
            uint32_t af[4][4], bf[4][2];
            #pragma unroll
            for (int mt = 0; mt < 4; ++mt){
                int arow = wm*64 + mt*16 + (lid & 15);
                ldm_x4(af[mt], base + (uint32_t)(arow*272 + s*32 + ((lid>>4)<<4)));
            }
            #pragma unroll
            for (int p = 0; p < 2; ++p){
                int brow = wc*32 + ((g>>1)<<3) + (lid & 7) + p*16;
                uint32_t rr[4];
                ldm_x4(rr, base + 34816u + (uint32_t)(brow*272 + s*32 + ((g&1)<<4)));
                bf[2*p][0] = rr[0]; bf[2*p][1] = rr[1];
                bf[2*p+1][0] = rr[2]; bf[2*p+1][1] = rr[3];
            }
            #pragma unroll
            for (int mt = 0; mt < 4; ++mt)
            #pragma unroll
            for (int nt = 0; nt < 4; ++nt)
                mma_f16(sr[mt][nt], af[mt], bf[nt]);
        }
        #pragma unroll
        for (int mt = 0; mt < 4; ++mt)
        #pragma unroll
        for (int nt = 0; nt < 4; ++nt){
            int r0 = wm*64 + mt*16 + (lid>>2);
            int c0 = wc*32 + nt*8 + (lid&3)*2;
            sr[mt][nt][0] += __half2float(smh[70656 + r0*264 + (r0 - c0 + 127)]);
            sr[mt][nt][1] += __half2float(smh[70656 + r0*264 + (r0 - c0 + 126)]);
            sr[mt][nt][2] += __half2float(smh[70656 + (r0+8)*264 + (r0 - c0 + 135)]);
            sr[mt][nt][3] += __half2float(smh[70656 + (r0+8)*264 + (r0 - c0 + 134)]);
        }
        __syncthreads();

        // ---- Ei -> sE ----
        egemm(128);
        __syncthreads();

        // ---- Si: A k-halves swapped, first half negated; gather Ei ----
        float si[4][4][4];
        #pragma unroll
        for (int a = 0; a < 4; ++a)
        #pragma unroll
        for (int b2 = 0; b2 < 4; ++b2)
        #pragma unroll
        for (int c = 0; c < 4; ++c) si[a][b2][c] = 0.f;
        #pragma unroll
        for (int s = 0; s < 8; ++s){
            int sa = (s < 4) ? s + 4 : s - 4;
            uint32_t af[4][4], bf[4][2];
            #pragma unroll
            for (int mt = 0; mt < 4; ++mt){
                int arow = wm*64 + mt*16 + (lid & 15);
                ldm_x4(af[mt], base + (uint32_t)(arow*272 + sa*32 + ((lid>>4)<<4)));
                if (s >= 4){
                    af[mt][0] ^= 0x80008000u; af[mt][1] ^= 0x80008000u;
                    af[mt][2] ^= 0x80008000u; af[mt][3] ^= 0x80008000u;
                }
            }
            #pragma unroll
            for (int p = 0; p < 2; ++p){
                int brow = wc*32 + ((g>>1)<<3) + (lid & 7) + p*16;
                uint32_t rr[4];
                ldm_x4(rr, base + 34816u + (uint32_t)(brow*272 + s*32 + ((g&1)<<4)));
                bf[2*p][0] = rr[0]; bf[2*p][1] = rr[1];
                bf[2*p+1][0] = rr[2]; bf[2*p+1][1] = rr[3];
            }
            #pragma unroll
            for (int mt = 0; mt < 4; ++mt)
            #pragma unroll
            for (int nt = 0; nt < 4; ++nt)
                mma_f16(si[mt][nt], af[mt], bf[nt]);
        }
        #pragma unroll
        for (int mt = 0; mt < 4; ++mt)
        #pragma unroll
        for (int nt = 0; nt < 4; ++nt){
            int r0 = wm*64 + mt*16 + (lid>>2);
            int c0 = wc*32 + nt*8 + (lid&3)*2;
            si[mt][nt][0] += __half2float(smh[70656 + r0*264 + (r0 - c0 + 127)]);
            si[mt][nt][1] += __half2float(smh[70656 + r0*264 + (r0 - c0 + 126)]);
            si[mt][nt][2] += __half2float(smh[70656 + (r0+8)*264 + (r0 - c0 + 135)]);
            si[mt][nt][3] += __half2float(smh[70656 + (r0+8)*264 + (r0 - c0 + 134)]);
        }

        // ---- magnitude (into sr) + row-max reduce ----
        #pragma unroll
        for (int mt = 0; mt < 4; ++mt)
        #pragma unroll
        for (int nt = 0; nt < 4; ++nt)
        #pragma unroll
        for (int e2 = 0; e2 < 4; ++e2)
            sr[mt][nt][e2] = 0.125f * sqrtf(sr[mt][nt][e2]*sr[mt][nt][e2] + si[mt][nt][e2]*si[mt][nt][e2]);

        #pragma unroll
        for (int mt = 0; mt < 4; ++mt)
        #pragma unroll
        for (int h2 = 0; h2 < 2; ++h2){
            float v = -1e30f;
            #pragma unroll
            for (int nt = 0; nt < 4; ++nt)
                v = fmaxf(v, fmaxf(sr[mt][nt][h2*2], sr[mt][nt][h2*2+1]));
            v = fmaxf(v, __shfl_xor_sync(0xffffffffu, v, 1));
            v = fmaxf(v, __shfl_xor_sync(0xffffffffu, v, 2));
            if ((lid & 3) == 0){
                int row = wm*64 + mt*16 + (lid>>2) + h2*8;
                sRed[row*4 + wc] = v;
            }
        }
        __syncthreads();
        if (tid < 128){
            float t = fmaxf(fmaxf(sRed[tid*4], sRed[tid*4+1]), fmaxf(sRed[tid*4+2], sRed[tid*4+3]));
            float mOld = mRow[tid], mNew = fmaxf(mOld, t);
            aRow[tid] = __expf(mOld - mNew);
            mRow[tid] = mNew;
        }
        __syncthreads();

        // ---- p = exp(mag - m), write sP (reuse E region, pitch 136h), sums, O rescale ----
        #pragma unroll
        for (int mt = 0; mt < 4; ++mt)
        #pragma unroll
        for (int h2 = 0; h2 < 2; ++h2){
            int row = wm*64 + mt*16 + (lid>>2) + h2*8;
            float mn = mRow[row], al = aRow[row];
            float ssum = 0.f;
            #pragma unroll
            for (int nt = 0; nt < 4; ++nt){
                float p0 = __expf(sr[mt][nt][h2*2]   - mn);
                float p1 = __expf(sr[mt][nt][h2*2+1] - mn);
                ssum += p0 + p1;
                int c0 = wc*32 + nt*8 + (lid&3)*2;
                *(__half2*)(smh + 70656 + row*136 + c0) = __floats2half2_rn(p0, p1);
                O[mt][nt][h2*2]   *= al;
                O[mt][nt][h2*2+1] *= al;
            }
            ssum += __shfl_xor_sync(0xffffffffu, ssum, 1);
            ssum += __shfl_xor_sync(0xffffffffu, ssum, 2);
            if ((lid & 3) == 0) sRed[row*4 + wc] = ssum;
        }
        __syncthreads();
        if (tid < 128)
            lRow[tid] = lRow[tid]*aRow[tid] + sRed[tid*4] + sRed[tid*4+1] + sRed[tid*4+2] + sRed[tid*4+3];

        // ---- O += sP * sV^T (K = 128 keys) ----
        #pragma unroll
        for (int s = 0; s < 8; ++s){
            uint32_t af[4][4], bf[4][2];
            #pragma unroll
            for (int mt = 0; mt < 4; ++mt){
                int arow = wm*64 + mt*16 + (lid & 15);
                ldm_x4(af[mt], base + 141312u + (uint32_t)(arow*272 + s*32 + ((lid>>4)<<4)));
            }
            #pragma unroll
            for (int p = 0; p < 2; ++p){
                int brow = wc*32 + ((g>>1)<<3) + (lid & 7) + p*16;
                uint32_t rr[4];
                ldm_x4(rr, base + 69632u + (uint32_t)(brow*272 + s*32 + ((g&1)<<4)));
                bf[2*p][0] = rr[0]; bf[2*p][1] = rr[1];
                bf[2*p+1][0] = rr[2]; bf[2*p+1][1] = rr[3];
            }
            #pragma unroll
            for (int mt = 0; mt < 4; ++mt)
            #pragma unroll
            for (int nt = 0; nt < 4; ++nt)
                mma_f16(O[mt][nt], af[mt], bf[nt]);
        }
        __syncthreads();
    }

    // ---- finalize: /l, hi/lo split, write gAo [m][2048] ----
    const int bb = bh >> 3, hh = bh & 7;
    #pragma unroll
    for (int mt = 0; mt < 4; ++mt)
    #pragma unroll
    for (int h2 = 0; h2 < 2; ++h2){
        int row = wm*64 + mt*16 + (lid>>2) + h2*8;
        float inv = 1.0f / lRow[row];
        int m = bb*1024 + i0 + row;
        #pragma unroll
        for (int nt = 0; nt < 4; ++nt){
            int c0 = wc*32 + nt*8 + (lid&3)*2;
            float v0 = O[mt][nt][h2*2] * inv, v1 = O[mt][nt][h2*2+1] * inv;
            __half h0, l0, h1, l1;
            hsplit(v0, h0, l0); hsplit(v1, h1, l1);
            int e0 = (c0 < 64) ? hh*64 + c0 : 512 + hh*64 + (c0 - 64);
            *(__half2*)(Ao + (size_t)m*2048 + e0)        = __halves2half2(h0, h1);
            *(__half2*)(Ao + (size_t)m*2048 + 1024 + e0) = __halves2half2(l0, l1);
        }
    }
}

// =====================================================================
// Prep / elementwise kernels
// =====================================================================
__global__ void k_prep_xA(const float2* __restrict__ x){
    int idx = blockIdx.x * 256 + threadIdx.x;
    int m = idx >> 10, ka = idx & 1023;
    float v = (ka < 512) ? x[(size_t)m*512 + ka].x : x[(size_t)m*512 + ka - 512].y;
    __half h, l; hsplit(v, h, l);
    size_t b = (size_t)m * 2048;
    gAq[b+ka] = h; gAq[b+1024+ka] = l;
}

__global__ void k_prep_qkvB(const float* __restrict__ wq_r, const float* __restrict__ wq_i,
                            const float* __restrict__ wkv_r, const float* __restrict__ wkv_i){
    int idx = blockIdx.x * 256 + threadIdx.x;
    int n = idx >> 10, k = idx & 1023;
    int ka = k & 511, isb = k >> 9;
    int im = n >= 1536;
    int c = im ? n - 1536 : n;
    const float* Wr = (c < 512) ? wq_r : wkv_r;
    const float* Wi = (c < 512) ? wq_i : wkv_i;
    int cc = (c < 512) ? c : c - 512;
    int ldw = (c < 512) ? 512 : 1024;
    float wr = Wr[(size_t)ka*ldw + cc], wi = Wi[(size_t)ka*ldw + cc];
    float v = im ? (isb ? wr : wi) : (isb ? -wi : wr);
    __half h = __float2half_rn(v);
    size_t b = (size_t)n * 2048;
    gBq[b+k] = h; gBq[b+1024+k] = h;
}

__global__ void k_prep_rel(const float* __restrict__ rel){
    int idx = blockIdx.x * 256 + threadIdx.x;
    if (idx < 1025*64) gBe[idx] = __float2half_rn(rel[idx]);
}

__global__ __launch_bounds__(256) void k_prep_attn(){
    __shared__ float sVr[64][65], sVi[64][65];
    const int bh = blockIdx.x, n0 = blockIdx.y << 6;
    const int b = bh >> 3, h = bh & 7;
    const int tid = threadIdx.x, dl = tid & 63;
    #pragma unroll
    for (int p = 0; p < 16; ++p){
        int nl = (p << 2) + (tid >> 6);
        int n = n0 + nl;
        size_t mrow = ((size_t)b*1024 + n) * 3072;
        int hd = h*64 + dl;
        float qr = gCq[mrow + hd],        qi = gCq[mrow + 1536 + hd];
        float kr = gCq[mrow + 512 + hd],  ki = gCq[mrow + 2048 + hd];
        float vr = gCq[mrow + 1024 + hd], vi = gCq[mrow + 2560 + hd];
        size_t qb = ((size_t)bh*1024 + n) * 128;
        gQf[qb+dl]    = __float2half_rn(qr);
        gQf[qb+64+dl] = __float2half_rn(qi);
        gKf[qb+dl]    = __float2half_rn(kr);
        gKf[qb+64+dl] = __float2half_rn(-ki);
        sVr[nl][dl] = vr; sVi[nl][dl] = vi;
    }
    __syncthreads();
    #pragma unroll
    for (int p = 0; p < 16; ++p){
        int d = (p << 2) + (tid >> 6);
        int n_ = tid & 63;
        gVf[((size_t)bh*128 + d)*1024 + n0 + n_]      = __float2half_rn(sVr[n_][d]);
        gVf[((size_t)bh*128 + 64 + d)*1024 + n0 + n_] = __float2half_rn(sVi[n_][d]);
    }
}

__global__ void k_prep_outB(const float* __restrict__ wo_r, const float* __restrict__ wo_i){
    int idx = blockIdx.x * 256 + threadIdx.x;
    int n = idx >> 10, k = idx & 1023;
    int c = n & 511, ka = k & 511;
    float wr = wo_r[(size_t)ka*512 + c], wi = wo_i[(size_t)ka*512 + c];
    float v = (n < 512) ? ((k < 512) ? wr : -wi) : ((k < 512) ? wi : wr);
    __half h = __float2half_rn(v);
    size_t bb = (size_t)n * 2048;
    gBo[bb+k] = h; gBo[bb+1024+k] = h;
}

__global__ void k_final(const float* __restrict__ bo_r, const float* __restrict__ bo_i,
                        float2* __restrict__ out){
    int idx = blockIdx.x * 256 + threadIdx.x;
    int m = idx >> 9, c = idx & 511;
    out[(size_t)m*512 + c] = make_float2(gCo[(size_t)m*1024 + c]       + bo_r[c],
                                         gCo[(size_t)m*1024 + 512 + c] + bo_i[c]);
}

// =====================================================================
extern "C" void kernel_launch(void* const* d_in, const int* in_sizes, int n_in,
                              void* d_out, int out_size)
{
    const float2* x    = (const float2*)d_in[0];
    const float* wq_r  = (const float*)d_in[1];
    const float* wq_i  = (const float*)d_in[2];
    const float* wkv_r = (const float*)d_in[3];
    const float* wkv_i = (const float*)d_in[4];
    const float* wo_r  = (const float*)d_in[5];
    const float* wo_i  = (const float*)d_in[6];
    const float* bo_r  = (const float*)d_in[7];
    const float* bo_i  = (const float*)d_in[8];
    const float* rel   = (const float*)d_in[9];

    cudaFuncSetAttribute(k_gemm, cudaFuncAttributeMaxDynamicSharedMemorySize, GSMEM);
    cudaFuncSetAttribute(k_attn_fused, cudaFuncAttributeMaxDynamicSharedMemorySize, FSMEM);

    void *pAq,*pBq,*pCq,*pQf,*pKf,*pVf,*pBe,*pAo,*pBo,*pCo;
    cudaGetSymbolAddress(&pAq, gAq);   cudaGetSymbolAddress(&pBq, gBq);
    cudaGetSymbolAddress(&pCq, gCq);   cudaGetSymbolAddress(&pQf, gQf);
    cudaGetSymbolAddress(&pKf, gKf);   cudaGetSymbolAddress(&pVf, gVf);
    cudaGetSymbolAddress(&pBe, gBe);   cudaGetSymbolAddress(&pAo, gAo);
    cudaGetSymbolAddress(&pBo, gBo);   cudaGetSymbolAddress(&pCo, gCo);

    k_prep_xA  <<<16384, 256>>>(x);
    k_prep_qkvB<<<12288, 256>>>(wq_r, wq_i, wkv_r, wkv_i);
    k_prep_rel <<<257, 256>>>(rel);
    k_prep_outB<<<4096, 256>>>(wo_r, wo_i);

    // QKV: C[4096,3072] = A[4096,2048] * B[3072,2048]^T
    k_gemm<<<dim3(32,24,1), 256, GSMEM>>>((__half*)pAq, (__half*)pBq, pCq,
        2048, 3072, 0LL, 0LL, 0LL, 0);
    k_prep_attn<<<dim3(32,16), 256>>>();
    // fused attention (S + rel + softmax + PV) -> gAo (hi/lo split)
    k_attn_fused<<<dim3(32,8), 256, FSMEM>>>((__half*)pQf, (__half*)pKf,
        (__half*)pVf, (__half*)pBe, (__half*)pAo);
    // OUT: [4096,1024] = A[4096,2048]*B[1024,2048]^T
    k_gemm<<<dim3(32,8,1), 256, GSMEM>>>((__half*)pAo, (__half*)pBo, pCo,
        2048, 1024, 0LL, 0LL, 0LL, 0);
    k_final<<<8192, 256>>>(bo_r, bo_i, (float2*)d_out);
}